// round 16
// baseline (speedup 1.0000x reference)
#include <cuda_runtime.h>
#include <cuda_fp16.h>
#include <cstdint>
#include <math.h>

#define BB 2
#define NN 2048
#define DD 768
#define HH 12
#define HD 64
#define BH (BB*HH)
#define XN (BB*NN*DD)
#define WN (DD*DD)
#define LOG2E 1.4426950408889634f

__device__ __align__(16) __half g_xh[XN], g_xl[XN];
__device__ __align__(16) __half g_wh[3 * WN], g_wl[3 * WN];
__device__ __align__(16) __half g_qh[BH*NN*HD], g_ql[BH*NN*HD];
__device__ __align__(16) __half g_kh[BH*NN*HD], g_kl[BH*NN*HD];
__device__ __align__(16) __half g_vh[BH*NN*HD];

// readiness flags: [n0i (6)][mtile (64)]  (mtile = 64-row tile of b*NN+n space)
__device__ int g_fq[384], g_fk[384], g_fv[384];

__device__ __forceinline__ uint32_t smem_u32(const void* p) {
    uint32_t a;
    asm("{ .reg .u64 t; cvta.to.shared.u64 t, %1; cvt.u32.u64 %0, t; }" : "=r"(a) : "l"(p));
    return a;
}
__device__ __forceinline__ uint32_t pack2h(float a, float b) {
    __half2 t = __floats2half2_rn(a, b);
    return *reinterpret_cast<uint32_t*>(&t);
}
__device__ __forceinline__ void split2h(float a, float b, uint32_t& hp, uint32_t& lp) {
    __half ha = __float2half_rn(a), hb = __float2half_rn(b);
    __half2 hh = __halves2half2(ha, hb);
    hp = *reinterpret_cast<uint32_t*>(&hh);
    lp = pack2h(a - __half2float(ha), b - __half2float(hb));
}
__device__ __forceinline__ void cpa16(uint32_t dst, const void* src) {
    asm volatile("cp.async.cg.shared.global [%0], [%1], 16;" :: "r"(dst), "l"(src) : "memory");
}
__device__ __forceinline__ void cpa_commit() {
    asm volatile("cp.async.commit_group;" ::: "memory");
}
__device__ __forceinline__ void ldmx4(uint32_t* r, uint32_t addr) {
    asm volatile("ldmatrix.sync.aligned.m8n8.x4.shared.b16 {%0,%1,%2,%3}, [%4];"
        : "=r"(r[0]), "=r"(r[1]), "=r"(r[2]), "=r"(r[3]) : "r"(addr));
}
__device__ __forceinline__ void ldmx4t(uint32_t* r, uint32_t addr) {
    asm volatile("ldmatrix.sync.aligned.m8n8.x4.trans.shared.b16 {%0,%1,%2,%3}, [%4];"
        : "=r"(r[0]), "=r"(r[1]), "=r"(r[2]), "=r"(r[3]) : "r"(addr));
}
__device__ __forceinline__ void mma16816(float* c, const uint32_t* a, uint32_t b0, uint32_t b1) {
    asm volatile("mma.sync.aligned.m16n8k16.row.col.f32.f16.f16.f32 "
        "{%0,%1,%2,%3}, {%4,%5,%6,%7}, {%8,%9}, {%0,%1,%2,%3};"
        : "+f"(c[0]), "+f"(c[1]), "+f"(c[2]), "+f"(c[3])
        : "r"(a[0]), "r"(a[1]), "r"(a[2]), "r"(a[3]), "r"(b0), "r"(b1));
}
__device__ __forceinline__ int ld_acq(const int* p) {
    int v;
    asm volatile("ld.acquire.gpu.global.b32 %0, [%1];" : "=r"(v) : "l"(p) : "memory");
    return v;
}
__device__ __forceinline__ void st_rel(int* p, int v) {
    asm volatile("st.release.gpu.global.b32 [%0], %1;" :: "l"(p), "r"(v) : "memory");
}
__device__ __forceinline__ void wait_flag(const int* f) {
    while (ld_acq(f) == 0) __nanosleep(128);
}

// ---------------------------------------------------------------------------
// Split kernel. Wq pre-scaled by log2(e). Block 0 zeroes flags each replay.
// ---------------------------------------------------------------------------
__global__ __launch_bounds__(256) void split_kernel(
    const float4* __restrict__ x, const float4* __restrict__ Wq,
    const float4* __restrict__ Wk, const float4* __restrict__ Wv)
{
    if (blockIdx.x == 0) {
        for (int i = threadIdx.x; i < 384; i += 256) {
            g_fq[i] = 0; g_fk[i] = 0; g_fv[i] = 0;
        }
        __threadfence();
    }
    const int nx = XN / 4, nw = WN / 4;
    int i = blockIdx.x * 256 + threadIdx.x;
    if (i >= nx + 3 * nw) return;

    float4 v;
    __half *hd, *ld;
    if (i < nx) {
        v = x[i];
        hd = g_xh + (size_t)i * 4; ld = g_xl + (size_t)i * 4;
    } else {
        int j = i - nx;
        int z = j / nw, r = j - z * nw;
        const float4* w = (z == 0) ? Wq : (z == 1) ? Wk : Wv;
        v = w[r];
        if (z == 0) { v.x *= LOG2E; v.y *= LOG2E; v.z *= LOG2E; v.w *= LOG2E; }
        hd = g_wh + (size_t)z * WN + (size_t)r * 4;
        ld = g_wl + (size_t)z * WN + (size_t)r * 4;
    }
    uint32_t h0, l0, h1, l1;
    split2h(v.x, v.y, h0, l0);
    split2h(v.z, v.w, h1, l1);
    *reinterpret_cast<uint2*>(hd) = make_uint2(h0, h1);
    *reinterpret_cast<uint2*>(ld) = make_uint2(l0, l1);
}

// ---------------------------------------------------------------------------
// Q/K projection (R14 body + flag publish). CTA 128x128, 8 warps x (32x64).
// ---------------------------------------------------------------------------
#define KC 32
#define SROW 40
#define T128_B (128 * SROW * 2)
#define QK_STAGE_B (4 * T128_B)
#define NCHUNK (DD / KC)

__global__ __launch_bounds__(256, 2) void qk_mma_kernel()
{
    extern __shared__ char smc[];
    const uint32_t sb = smem_u32(smc);

    const int tid = threadIdx.x;
    const int w = tid >> 5, lane = tid & 31;
    const int wm = (w >> 1) * 32;
    const int wn = (w & 1) * 64;
    const int z = blockIdx.z;
    const int n0 = blockIdx.x * 128;
    const int m0 = blockIdx.y * 128;

    const __half* __restrict__ Bhp = g_wh + (size_t)z * WN;
    const __half* __restrict__ Blp = g_wl + (size_t)z * WN;

    auto load_chunk = [&](int kt, int stage) {
        const int kb = kt * KC;
        const uint32_t st = sb + stage * QK_STAGE_B;
        #pragma unroll
        for (int i = 0; i < 2; ++i) {
            int id = tid + i * 256;
            int r = id >> 2, c = id & 3;
            uint32_t doff = (uint32_t)(r * 80 + c * 16);
            size_t gA = (size_t)(m0 + r) * DD + kb + c * 8;
            size_t gB = (size_t)(n0 + r) * DD + kb + c * 8;
            cpa16(st + 0 * T128_B + doff, g_xh + gA);
            cpa16(st + 1 * T128_B + doff, g_xl + gA);
            cpa16(st + 2 * T128_B + doff, Bhp + gB);
            cpa16(st + 3 * T128_B + doff, Blp + gB);
        }
        cpa_commit();
    };

    float acc[2][8][4] = {};

    load_chunk(0, 0);
    load_chunk(1, 1);

    const int lrow = lane & 15;
    const int lcol = ((lane >> 4) & 1) * 8;

    for (int kt = 0; kt < NCHUNK; ++kt) {
        if (kt < NCHUNK - 1)
            asm volatile("cp.async.wait_group 1;" ::: "memory");
        else
            asm volatile("cp.async.wait_group 0;" ::: "memory");
        __syncthreads();

        const uint32_t st = sb + (kt & 1) * QK_STAGE_B;

        #pragma unroll
        for (int ks = 0; ks < 2; ++ks) {
            const int kc = ks * 16 + lcol;
            uint32_t bh[4][4], bl[4][4];
            #pragma unroll
            for (int fp = 0; fp < 4; ++fp) {
                uint32_t off = (uint32_t)((wn + fp * 16 + lrow) * SROW + kc) * 2;
                ldmx4(bh[fp], st + 2 * T128_B + off);
                ldmx4(bl[fp], st + 3 * T128_B + off);
            }
            #pragma unroll
            for (int mf = 0; mf < 2; ++mf) {
                uint32_t ah[4], al[4];
                uint32_t off = (uint32_t)((wm + mf * 16 + lrow) * SROW + kc) * 2;
                ldmx4(ah, st + 0 * T128_B + off);
                ldmx4(al, st + 1 * T128_B + off);
                #pragma unroll
                for (int fn = 0; fn < 8; ++fn) {
                    const int p = fn >> 1, f = fn & 1;
                    mma16816(acc[mf][fn], ah, bh[p][f], bh[p][f + 2]);
                }
                #pragma unroll
                for (int fn = 0; fn < 8; ++fn) {
                    const int p = fn >> 1, f = fn & 1;
                    mma16816(acc[mf][fn], ah, bl[p][f], bl[p][f + 2]);
                }
                #pragma unroll
                for (int fn = 0; fn < 8; ++fn) {
                    const int p = fn >> 1, f = fn & 1;
                    mma16816(acc[mf][fn], al, bh[p][f], bh[p][f + 2]);
                }
            }
        }
        __syncthreads();
        if (kt + 2 < NCHUNK) load_chunk(kt + 2, kt & 1);
    }

    __half* Oh = (z == 0) ? g_qh : g_kh;
    __half* Ol = (z == 0) ? g_ql : g_kl;
    const int trow = lane >> 2;
    const int tcol = (lane & 3) * 2;
    #pragma unroll
    for (int mf = 0; mf < 2; ++mf) {
        #pragma unroll
        for (int fn = 0; fn < 8; ++fn) {
            int o = n0 + wn + fn * 8 + tcol;
            int h = o >> 6, cb = o & 63;
            #pragma unroll
            for (int half = 0; half < 2; ++half) {
                int row = m0 + wm + mf * 16 + trow + half * 8;
                int b = row >> 11, n = row & (NN - 1);
                size_t idx = (((size_t)(b * HH + h)) * NN + n) * HD + cb;
                uint32_t hp, lp;
                split2h(acc[mf][fn][half * 2], acc[mf][fn][half * 2 + 1], hp, lp);
                *reinterpret_cast<uint32_t*>(Oh + idx) = hp;
                *reinterpret_cast<uint32_t*>(Ol + idx) = lp;
            }
        }
    }
    __syncthreads();
    if (tid == 0) {
        __threadfence();
        int* fl = (z == 0) ? g_fq : g_fk;
        st_rel(&fl[blockIdx.x * 64 + 2 * blockIdx.y + 0], 1);
        st_rel(&fl[blockIdx.x * 64 + 2 * blockIdx.y + 1], 1);
    }
}

// ---------------------------------------------------------------------------
// V projection (R14 body + flag publish). CTA 128x128.
// ---------------------------------------------------------------------------
#define V_STAGE_B (2 * T128_B)

__global__ __launch_bounds__(256, 2) void v_mma_kernel()
{
    extern __shared__ char smc[];
    const uint32_t sb = smem_u32(smc);

    const int tid = threadIdx.x;
    const int w = tid >> 5, lane = tid & 31;
    const int wm = (w >> 1) * 32;
    const int wn = (w & 1) * 64;
    const int n0 = blockIdx.x * 128;
    const int m0 = blockIdx.y * 128;

    const __half* __restrict__ Bhp = g_wh + (size_t)2 * WN;

    auto load_chunk = [&](int kt, int stage) {
        const int kb = kt * KC;
        const uint32_t st = sb + stage * V_STAGE_B;
        #pragma unroll
        for (int i = 0; i < 2; ++i) {
            int id = tid + i * 256;
            int r = id >> 2, c = id & 3;
            uint32_t doff = (uint32_t)(r * 80 + c * 16);
            cpa16(st + doff, g_xh + (size_t)(m0 + r) * DD + kb + c * 8);
            cpa16(st + T128_B + doff, Bhp + (size_t)(n0 + r) * DD + kb + c * 8);
        }
        cpa_commit();
    };

    float acc[2][8][4] = {};

    load_chunk(0, 0);
    load_chunk(1, 1);

    const int lrow = lane & 15;
    const int lcol = ((lane >> 4) & 1) * 8;

    for (int kt = 0; kt < NCHUNK; ++kt) {
        if (kt < NCHUNK - 1)
            asm volatile("cp.async.wait_group 1;" ::: "memory");
        else
            asm volatile("cp.async.wait_group 0;" ::: "memory");
        __syncthreads();

        const uint32_t st = sb + (kt & 1) * V_STAGE_B;

        #pragma unroll
        for (int ks = 0; ks < 2; ++ks) {
            const int kc = ks * 16 + lcol;
            uint32_t bh[4][4];
            #pragma unroll
            for (int fp = 0; fp < 4; ++fp) {
                uint32_t off = (uint32_t)((wn + fp * 16 + lrow) * SROW + kc) * 2;
                ldmx4(bh[fp], st + T128_B + off);
            }
            #pragma unroll
            for (int mf = 0; mf < 2; ++mf) {
                uint32_t ah[4];
                uint32_t off = (uint32_t)((wm + mf * 16 + lrow) * SROW + kc) * 2;
                ldmx4(ah, st + off);
                #pragma unroll
                for (int fn = 0; fn < 8; ++fn) {
                    const int p = fn >> 1, f = fn & 1;
                    mma16816(acc[mf][fn], ah, bh[p][f], bh[p][f + 2]);
                }
            }
        }
        __syncthreads();
        if (kt + 2 < NCHUNK) load_chunk(kt + 2, kt & 1);
    }

    const int trow = lane >> 2;
    const int tcol = (lane & 3) * 2;
    #pragma unroll
    for (int mf = 0; mf < 2; ++mf) {
        #pragma unroll
        for (int fn = 0; fn < 8; ++fn) {
            int o = n0 + wn + fn * 8 + tcol;
            int h = o >> 6, cb = o & 63;
            #pragma unroll
            for (int half = 0; half < 2; ++half) {
                int row = m0 + wm + mf * 16 + trow + half * 8;
                int b = row >> 11, n = row & (NN - 1);
                size_t idx = (((size_t)(b * HH + h)) * NN + n) * HD + cb;
                *reinterpret_cast<uint32_t*>(g_vh + idx) =
                    pack2h(acc[mf][fn][half * 2], acc[mf][fn][half * 2 + 1]);
            }
        }
    }
    __syncthreads();
    if (tid == 0) {
        __threadfence();
        st_rel(&g_fv[blockIdx.x * 64 + 2 * blockIdx.y + 0], 1);
        st_rel(&g_fv[blockIdx.x * 64 + 2 * blockIdx.y + 1], 1);
    }
}

// ---------------------------------------------------------------------------
// Flash attention (R14 body + flag waits). Runs on least-priority stream so
// producer CTAs always win free slots -> bounded waits.
// ---------------------------------------------------------------------------
#define VROW 72
#define QT_B (64 * VROW * 2)
#define KVTILE_B (64 * VROW * 2)
#define KVSTAGE_B (3 * KVTILE_B)

__global__ __launch_bounds__(128, 3) void flash_mma_kernel(float* __restrict__ out)
{
    extern __shared__ char smc[];
    const uint32_t sb = smem_u32(smc);
    const uint32_t sQh = sb;
    const uint32_t sQl = sb + QT_B;
    const uint32_t sKV = sb + 2 * QT_B;

    const int tid = threadIdx.x, wid = tid >> 5, lane = tid & 31;
    const int bh = blockIdx.y;
    const int qt = (int)gridDim.x - 1 - (int)blockIdx.x;   // heavy tiles first
    const int qbase = qt * 64;
    const int wm = wid * 16;
    const int rowmax = qbase + wm + 15;
    const int b = bh / HH, h = bh % HH;
    const int fbase = (h >> 1) * 64 + b * 32;

    const size_t base = (size_t)bh * NN * HD;
    const __half* __restrict__ Qhp = g_qh + base;
    const __half* __restrict__ Qlp = g_ql + base;
    const __half* __restrict__ Khp = g_kh + base;
    const __half* __restrict__ Klp = g_kl + base;
    const __half* __restrict__ Vhp = g_vh + base;

    auto load_kv = [&](int j, int stage) {
        wait_flag(&g_fk[fbase + j]);
        wait_flag(&g_fv[fbase + j]);
        const int kb = j * 64;
        const uint32_t st = sKV + stage * KVSTAGE_B;
        #pragma unroll
        for (int i = 0; i < 4; ++i) {
            int id = tid + i * 128;
            int r = id >> 3, c = id & 7;
            uint32_t doff = (uint32_t)(r * 144 + c * 16);
            size_t go = (size_t)(kb + r) * HD + c * 8;
            cpa16(st + 0 * KVTILE_B + doff, Khp + go);
            cpa16(st + 1 * KVTILE_B + doff, Klp + go);
            cpa16(st + 2 * KVTILE_B + doff, Vhp + go);
        }
        cpa_commit();
    };

    // Q tile (hi+lo) into smem after its flag; joins commit group 0
    wait_flag(&g_fq[fbase + qt]);
    #pragma unroll
    for (int i = 0; i < 4; ++i) {
        int id = tid + i * 128;
        int r = id >> 3, c = id & 7;
        uint32_t doff = (uint32_t)(r * 144 + c * 16);
        size_t go = (size_t)(qbase + r) * HD + c * 8;
        cpa16(sQh + doff, Qhp + go);
        cpa16(sQl + doff, Qlp + go);
    }

    float o[8][4] = {};
    float mi0 = -1e30f, mi1 = -1e30f;
    uint32_t mip;
    {
        __half2 t = __floats2half2_rn(-1e30f, -1e30f);
        mip = *reinterpret_cast<uint32_t*>(&t);
    }
    float li0 = 0.0f, li1 = 0.0f;

    const int ntiles = qt + 1;
    load_kv(0, 0);
    if (ntiles > 1) load_kv(1, 1);

    const int lrow = lane & 15;
    const int lcol = ((lane >> 4) & 1) * 8;
    const int vrow_base = (lane & 7) + ((lane >> 3) & 1) * 8;
    const int vcol = ((lane >> 4) & 1) * 8;

    for (int j = 0; j < ntiles; ++j) {
        if (j < ntiles - 1)
            asm volatile("cp.async.wait_group 1;" ::: "memory");
        else
            asm volatile("cp.async.wait_group 0;" ::: "memory");
        __syncthreads();

        const int j64 = 64 * j;
        const int nlim = rowmax - j64;
        const uint32_t st = sKV + (j & 1) * KVSTAGE_B;

        float s[8][4] = {};

        if (j < qt) {
            #pragma unroll
            for (int kk = 0; kk < 4; ++kk) {
                const int kc = kk * 16 + lcol;
                uint32_t qoff = (uint32_t)((wm + lrow) * VROW + kc) * 2;
                uint32_t qhf[4], qlf[4];
                ldmx4(qhf, sQh + qoff);
                ldmx4(qlf, sQl + qoff);
                uint32_t bh_[4][4], bl_[4][4];
                #pragma unroll
                for (int np = 0; np < 4; ++np) {
                    uint32_t off = (uint32_t)((np * 16 + lrow) * VROW + kc) * 2;
                    ldmx4(bh_[np], st + 0 * KVTILE_B + off);
                    ldmx4(bl_[np], st + 1 * KVTILE_B + off);
                }
                #pragma unroll
                for (int np = 0; np < 4; ++np) {
                    mma16816(s[np*2 + 0], qhf, bh_[np][0], bh_[np][2]);
                    mma16816(s[np*2 + 1], qhf, bh_[np][1], bh_[np][3]);
                }
                #pragma unroll
                for (int np = 0; np < 4; ++np) {
                    mma16816(s[np*2 + 0], qhf, bl_[np][0], bl_[np][2]);
                    mma16816(s[np*2 + 1], qhf, bl_[np][1], bl_[np][3]);
                }
                #pragma unroll
                for (int np = 0; np < 4; ++np) {
                    mma16816(s[np*2 + 0], qlf, bh_[np][0], bh_[np][2]);
                    mma16816(s[np*2 + 1], qlf, bh_[np][1], bh_[np][3]);
                }
            }
        } else {
            #pragma unroll
            for (int kk = 0; kk < 4; ++kk) {
                const int kc = kk * 16 + lcol;
                uint32_t qoff = (uint32_t)((wm + lrow) * VROW + kc) * 2;
                uint32_t qhf[4], qlf[4];
                ldmx4(qhf, sQh + qoff);
                ldmx4(qlf, sQl + qoff);
                #pragma unroll
                for (int np = 0; np < 4; ++np) {
                    if (np * 16 <= nlim) {
                        uint32_t bkh[4], bkl[4];
                        uint32_t off = (uint32_t)((np * 16 + lrow) * VROW + kc) * 2;
                        ldmx4(bkh, st + 0 * KVTILE_B + off);
                        ldmx4(bkl, st + 1 * KVTILE_B + off);
                        const int fn0 = np * 2;
                        mma16816(s[fn0 + 0], qhf, bkh[0], bkh[2]);
                        mma16816(s[fn0 + 1], qhf, bkh[1], bkh[3]);
                        mma16816(s[fn0 + 0], qhf, bkl[0], bkl[2]);
                        mma16816(s[fn0 + 1], qhf, bkl[1], bkl[3]);
                        mma16816(s[fn0 + 0], qlf, bkh[0], bkh[2]);
                        mma16816(s[fn0 + 1], qlf, bkh[1], bkh[3]);
                    }
                }
            }
            const int rg0 = qbase + wm + (lane >> 2);
            #pragma unroll
            for (int fn = 0; fn < 8; ++fn) {
                const int cb = j64 + fn * 8 + (lane & 3) * 2;
                if (cb + 0 > rg0)     s[fn][0] = -1e30f;
                if (cb + 1 > rg0)     s[fn][1] = -1e30f;
                if (cb + 0 > rg0 + 8) s[fn][2] = -1e30f;
                if (cb + 1 > rg0 + 8) s[fn][3] = -1e30f;
            }
        }

        // ---- online softmax ----
        {
            float m0n = mi0, m1n = mi1;
            #pragma unroll
            for (int fn = 0; fn < 8; ++fn) {
                m0n = fmaxf(m0n, fmaxf(s[fn][0], s[fn][1]));
                m1n = fmaxf(m1n, fmaxf(s[fn][2], s[fn][3]));
            }
            __half2 mp = __floats2half2_rn(m0n, m1n);
            uint32_t mu = *reinterpret_cast<uint32_t*>(&mp);
            uint32_t t1 = __shfl_xor_sync(0xffffffffu, mu, 1);
            mp = __hmax2(mp, *reinterpret_cast<__half2*>(&t1));
            mu = *reinterpret_cast<uint32_t*>(&mp);
            uint32_t t2 = __shfl_xor_sync(0xffffffffu, mu, 2);
            mp = __hmax2(mp, *reinterpret_cast<__half2*>(&t2));
            mu = *reinterpret_cast<uint32_t*>(&mp);

            const float m0f = __low2float(mp);
            const float m1f = __high2float(mp);

            if (mu != mip) {
                const float al0 = exp2f(mi0 - m0f);
                const float al1 = exp2f(mi1 - m1f);
                li0 *= al0; li1 *= al1;
                #pragma unroll
                for (int fn = 0; fn < 8; ++fn) {
                    o[fn][0] *= al0; o[fn][1] *= al0;
                    o[fn][2] *= al1; o[fn][3] *= al1;
                }
                mi0 = m0f; mi1 = m1f; mip = mu;
            }

            float rs0 = 0.0f, rs1 = 0.0f;
            #pragma unroll
            for (int fn = 0; fn < 8; ++fn) {
                s[fn][0] = exp2f(s[fn][0] - mi0);
                s[fn][1] = exp2f(s[fn][1] - mi0);
                s[fn][2] = exp2f(s[fn][2] - mi1);
                s[fn][3] = exp2f(s[fn][3] - mi1);
                rs0 += s[fn][0] + s[fn][1];
                rs1 += s[fn][2] + s[fn][3];
            }
            li0 += rs0;
            li1 += rs1;
        }

        // ---- pack P ----
        uint32_t ph[4][4];
        #pragma unroll
        for (int kk = 0; kk < 4; ++kk) {
            ph[kk][0] = pack2h(s[2*kk    ][0], s[2*kk    ][1]);
            ph[kk][1] = pack2h(s[2*kk    ][2], s[2*kk    ][3]);
            ph[kk][2] = pack2h(s[2*kk + 1][0], s[2*kk + 1][1]);
            ph[kk][3] = pack2h(s[2*kk + 1][2], s[2*kk + 1][3]);
        }

        // ---- O += P V ----
        if (j < qt) {
            #pragma unroll
            for (int kk = 0; kk < 4; ++kk) {
                uint32_t v0[4], v1[4], v2[4], v3[4];
                const int vrow = kk * 16 + vrow_base;
                uint32_t offb = (uint32_t)(vrow * VROW + vcol) * 2;
                ldmx4t(v0, st + 2 * KVTILE_B + offb + 0 * 32);
                ldmx4t(v1, st + 2 * KVTILE_B + offb + 1 * 32);
                ldmx4t(v2, st + 2 * KVTILE_B + offb + 2 * 32);
                ldmx4t(v3, st + 2 * KVTILE_B + offb + 3 * 32);
                mma16816(o[0], ph[kk], v0[0], v0[1]);
                mma16816(o[1], ph[kk], v0[2], v0[3]);
                mma16816(o[2], ph[kk], v1[0], v1[1]);
                mma16816(o[3], ph[kk], v1[2], v1[3]);
                mma16816(o[4], ph[kk], v2[0], v2[1]);
                mma16816(o[5], ph[kk], v2[2], v2[3]);
                mma16816(o[6], ph[kk], v3[0], v3[1]);
                mma16816(o[7], ph[kk], v3[2], v3[3]);
            }
        } else {
            #pragma unroll
            for (int kk = 0; kk < 4; ++kk) {
                if (kk * 16 <= nlim) {
                    #pragma unroll
                    for (int dp = 0; dp < 4; ++dp) {
                        const int vrow = kk * 16 + vrow_base;
                        uint32_t off = (uint32_t)(vrow * VROW + dp * 16 + vcol) * 2;
                        uint32_t vh_[4];
                        ldmx4t(vh_, st + 2 * KVTILE_B + off);
                        mma16816(o[dp*2 + 0], ph[kk], vh_[0], vh_[1]);
                        mma16816(o[dp*2 + 1], ph[kk], vh_[2], vh_[3]);
                    }
                }
            }
        }

        __syncthreads();
        if (j + 2 < ntiles) load_kv(j + 2, j & 1);
    }

    // ---- epilogue ----
    li0 += __shfl_xor_sync(0xffffffffu, li0, 1);
    li0 += __shfl_xor_sync(0xffffffffu, li0, 2);
    li1 += __shfl_xor_sync(0xffffffffu, li1, 1);
    li1 += __shfl_xor_sync(0xffffffffu, li1, 2);

    const float inv0 = 1.0f / li0, inv1 = 1.0f / li1;
    const int r0 = qbase + wm + (lane >> 2);
    const int c0 = (lane & 3) * 2;
    #pragma unroll
    for (int fn = 0; fn < 8; ++fn) {
        const int col = h * HD + fn * 8 + c0;
        float* d0 = out + ((size_t)(b * NN + r0)) * DD + col;
        float* d1 = out + ((size_t)(b * NN + r0 + 8)) * DD + col;
        *reinterpret_cast<float2*>(d0) = make_float2(o[fn][0] * inv0, o[fn][1] * inv0);
        *reinterpret_cast<float2*>(d1) = make_float2(o[fn][2] * inv1, o[fn][3] * inv1);
    }
}

static const int QK_SMEM    = 2 * QK_STAGE_B;             // 81920
static const int V_SMEM     = 2 * V_STAGE_B;              // 40960
static const int FLASH_SMEM = 2 * QT_B + 2 * KVSTAGE_B;   // 73728

extern "C" void kernel_launch(void* const* d_in, const int* in_sizes, int n_in,
                              void* d_out, int out_size)
{
    const float* x  = (const float*)d_in[0];
    const float* Wq = (const float*)d_in[1];
    const float* Wk = (const float*)d_in[2];
    const float* Wv = (const float*)d_in[3];
    float* out = (float*)d_out;

    // one-time resources (first call is not captured)
    static cudaStream_t s_qk = nullptr, s_v = nullptr, s_f = nullptr;
    static cudaEvent_t e_split = nullptr, e_qk = nullptr, e_v = nullptr, e_f = nullptr;
    if (s_qk == nullptr) {
        int lo, hi;  // lo = least priority (largest num), hi = greatest (smallest num)
        cudaDeviceGetStreamPriorityRange(&lo, &hi);
        cudaStreamCreateWithPriority(&s_qk, cudaStreamNonBlocking, hi);  // producers: high
        cudaStreamCreateWithPriority(&s_v,  cudaStreamNonBlocking, hi);
        cudaStreamCreateWithPriority(&s_f,  cudaStreamNonBlocking, lo);  // flash: low
        cudaEventCreateWithFlags(&e_split, cudaEventDisableTiming);
        cudaEventCreateWithFlags(&e_qk, cudaEventDisableTiming);
        cudaEventCreateWithFlags(&e_v, cudaEventDisableTiming);
        cudaEventCreateWithFlags(&e_f, cudaEventDisableTiming);
        cudaFuncSetAttribute(qk_mma_kernel, cudaFuncAttributeMaxDynamicSharedMemorySize, QK_SMEM);
        cudaFuncSetAttribute(v_mma_kernel, cudaFuncAttributeMaxDynamicSharedMemorySize, V_SMEM);
        cudaFuncSetAttribute(flash_mma_kernel, cudaFuncAttributeMaxDynamicSharedMemorySize, FLASH_SMEM);
    }

    // split (also zeroes flags) on the capture/origin stream
    int total4 = XN / 4 + 3 * (WN / 4);
    split_kernel<<<(total4 + 255) / 256, 256>>>(
        (const float4*)x, (const float4*)Wq, (const float4*)Wk, (const float4*)Wv);

    cudaEventRecord(e_split, 0);
    cudaStreamWaitEvent(s_qk, e_split, 0);
    cudaStreamWaitEvent(s_v, e_split, 0);
    cudaStreamWaitEvent(s_f, e_split, 0);

    // producers (high priority) and flash (low priority, flag-synchronized)
    qk_mma_kernel<<<dim3(DD / 128, (BB * NN) / 128, 2), 256, QK_SMEM, s_qk>>>();
    v_mma_kernel<<<dim3(DD / 128, (BB * NN) / 128), 256, V_SMEM, s_v>>>();
    flash_mma_kernel<<<dim3(NN / 64, BH), 128, FLASH_SMEM, s_f>>>(out);

    // join everything back to the origin stream
    cudaEventRecord(e_qk, s_qk);
    cudaEventRecord(e_v, s_v);
    cudaEventRecord(e_f, s_f);
    cudaStreamWaitEvent(0, e_qk, 0);
    cudaStreamWaitEvent(0, e_v, 0);
    cudaStreamWaitEvent(0, e_f, 0);
}

// round 17
// speedup vs baseline: 1.0183x; 1.0183x over previous
#include <cuda_runtime.h>
#include <cuda_fp16.h>
#include <cstdint>
#include <math.h>

#define BB 2
#define NN 2048
#define DD 768
#define HH 12
#define HD 64
#define BH (BB*HH)
#define XN (BB*NN*DD)
#define WN (DD*DD)
#define LOG2E 1.4426950408889634f
#define ONES2 0x3C003C00u   // half2 (1.0, 1.0)

__device__ __align__(16) __half g_xh[XN], g_xl[XN];
__device__ __align__(16) __half g_wh[3 * WN], g_wl[3 * WN];
__device__ __align__(16) __half g_qh[BH*NN*HD], g_ql[BH*NN*HD];
__device__ __align__(16) __half g_kh[BH*NN*HD], g_kl[BH*NN*HD];
__device__ __align__(16) __half g_vh[BH*NN*HD];

__device__ __forceinline__ uint32_t smem_u32(const void* p) {
    uint32_t a;
    asm("{ .reg .u64 t; cvta.to.shared.u64 t, %1; cvt.u32.u64 %0, t; }" : "=r"(a) : "l"(p));
    return a;
}
__device__ __forceinline__ uint32_t pack2h(float a, float b) {
    __half2 t = __floats2half2_rn(a, b);
    return *reinterpret_cast<uint32_t*>(&t);
}
__device__ __forceinline__ uint32_t hex2(uint32_t a) {
    uint32_t d;
    asm("ex2.approx.f16x2 %0, %1;" : "=r"(d) : "r"(a));
    return d;
}
__device__ __forceinline__ void split2h(float a, float b, uint32_t& hp, uint32_t& lp) {
    __half ha = __float2half_rn(a), hb = __float2half_rn(b);
    __half2 hh = __halves2half2(ha, hb);
    hp = *reinterpret_cast<uint32_t*>(&hh);
    lp = pack2h(a - __half2float(ha), b - __half2float(hb));
}
__device__ __forceinline__ void cpa16(uint32_t dst, const void* src) {
    asm volatile("cp.async.cg.shared.global [%0], [%1], 16;" :: "r"(dst), "l"(src) : "memory");
}
__device__ __forceinline__ void cpa_commit() {
    asm volatile("cp.async.commit_group;" ::: "memory");
}
__device__ __forceinline__ void ldmx4(uint32_t* r, uint32_t addr) {
    asm volatile("ldmatrix.sync.aligned.m8n8.x4.shared.b16 {%0,%1,%2,%3}, [%4];"
        : "=r"(r[0]), "=r"(r[1]), "=r"(r[2]), "=r"(r[3]) : "r"(addr));
}
__device__ __forceinline__ void ldmx4t(uint32_t* r, uint32_t addr) {
    asm volatile("ldmatrix.sync.aligned.m8n8.x4.trans.shared.b16 {%0,%1,%2,%3}, [%4];"
        : "=r"(r[0]), "=r"(r[1]), "=r"(r[2]), "=r"(r[3]) : "r"(addr));
}
__device__ __forceinline__ void mma16816(float* c, const uint32_t* a, uint32_t b0, uint32_t b1) {
    asm volatile("mma.sync.aligned.m16n8k16.row.col.f32.f16.f16.f32 "
        "{%0,%1,%2,%3}, {%4,%5,%6,%7}, {%8,%9}, {%0,%1,%2,%3};"
        : "+f"(c[0]), "+f"(c[1]), "+f"(c[2]), "+f"(c[3])
        : "r"(a[0]), "r"(a[1]), "r"(a[2]), "r"(a[3]), "r"(b0), "r"(b1));
}

// ---------------------------------------------------------------------------
// Split kernel. Wq pre-scaled by log2(e).
// ---------------------------------------------------------------------------
__global__ __launch_bounds__(256) void split_kernel(
    const float4* __restrict__ x, const float4* __restrict__ Wq,
    const float4* __restrict__ Wk, const float4* __restrict__ Wv)
{
    const int nx = XN / 4, nw = WN / 4;
    int i = blockIdx.x * 256 + threadIdx.x;
    if (i >= nx + 3 * nw) return;

    float4 v;
    __half *hd, *ld;
    if (i < nx) {
        v = x[i];
        hd = g_xh + (size_t)i * 4; ld = g_xl + (size_t)i * 4;
    } else {
        int j = i - nx;
        int z = j / nw, r = j - z * nw;
        const float4* w = (z == 0) ? Wq : (z == 1) ? Wk : Wv;
        v = w[r];
        if (z == 0) { v.x *= LOG2E; v.y *= LOG2E; v.z *= LOG2E; v.w *= LOG2E; }
        hd = g_wh + (size_t)z * WN + (size_t)r * 4;
        ld = g_wl + (size_t)z * WN + (size_t)r * 4;
    }
    uint32_t h0, l0, h1, l1;
    split2h(v.x, v.y, h0, l0);
    split2h(v.z, v.w, h1, l1);
    *reinterpret_cast<uint2*>(hd) = make_uint2(h0, h1);
    *reinterpret_cast<uint2*>(ld) = make_uint2(l0, l1);
}

// ---------------------------------------------------------------------------
// Q/K projection (R14 best, unchanged).
// ---------------------------------------------------------------------------
#define KC 32
#define SROW 40
#define T128_B (128 * SROW * 2)
#define QK_STAGE_B (4 * T128_B)
#define NCHUNK (DD / KC)

__global__ __launch_bounds__(256, 2) void qk_mma_kernel()
{
    extern __shared__ char smc[];
    const uint32_t sb = smem_u32(smc);

    const int tid = threadIdx.x;
    const int w = tid >> 5, lane = tid & 31;
    const int wm = (w >> 1) * 32;
    const int wn = (w & 1) * 64;
    const int z = blockIdx.z;
    const int n0 = blockIdx.x * 128;
    const int m0 = blockIdx.y * 128;

    const __half* __restrict__ Bhp = g_wh + (size_t)z * WN;
    const __half* __restrict__ Blp = g_wl + (size_t)z * WN;

    auto load_chunk = [&](int kt, int stage) {
        const int kb = kt * KC;
        const uint32_t st = sb + stage * QK_STAGE_B;
        #pragma unroll
        for (int i = 0; i < 2; ++i) {
            int id = tid + i * 256;
            int r = id >> 2, c = id & 3;
            uint32_t doff = (uint32_t)(r * 80 + c * 16);
            size_t gA = (size_t)(m0 + r) * DD + kb + c * 8;
            size_t gB = (size_t)(n0 + r) * DD + kb + c * 8;
            cpa16(st + 0 * T128_B + doff, g_xh + gA);
            cpa16(st + 1 * T128_B + doff, g_xl + gA);
            cpa16(st + 2 * T128_B + doff, Bhp + gB);
            cpa16(st + 3 * T128_B + doff, Blp + gB);
        }
        cpa_commit();
    };

    float acc[2][8][4] = {};

    load_chunk(0, 0);
    load_chunk(1, 1);

    const int lrow = lane & 15;
    const int lcol = ((lane >> 4) & 1) * 8;

    for (int kt = 0; kt < NCHUNK; ++kt) {
        if (kt < NCHUNK - 1)
            asm volatile("cp.async.wait_group 1;" ::: "memory");
        else
            asm volatile("cp.async.wait_group 0;" ::: "memory");
        __syncthreads();

        const uint32_t st = sb + (kt & 1) * QK_STAGE_B;

        #pragma unroll
        for (int ks = 0; ks < 2; ++ks) {
            const int kc = ks * 16 + lcol;
            uint32_t bh[4][4], bl[4][4];
            #pragma unroll
            for (int fp = 0; fp < 4; ++fp) {
                uint32_t off = (uint32_t)((wn + fp * 16 + lrow) * SROW + kc) * 2;
                ldmx4(bh[fp], st + 2 * T128_B + off);
                ldmx4(bl[fp], st + 3 * T128_B + off);
            }
            #pragma unroll
            for (int mf = 0; mf < 2; ++mf) {
                uint32_t ah[4], al[4];
                uint32_t off = (uint32_t)((wm + mf * 16 + lrow) * SROW + kc) * 2;
                ldmx4(ah, st + 0 * T128_B + off);
                ldmx4(al, st + 1 * T128_B + off);
                #pragma unroll
                for (int fn = 0; fn < 8; ++fn) {
                    const int p = fn >> 1, f = fn & 1;
                    mma16816(acc[mf][fn], ah, bh[p][f], bh[p][f + 2]);
                }
                #pragma unroll
                for (int fn = 0; fn < 8; ++fn) {
                    const int p = fn >> 1, f = fn & 1;
                    mma16816(acc[mf][fn], ah, bl[p][f], bl[p][f + 2]);
                }
                #pragma unroll
                for (int fn = 0; fn < 8; ++fn) {
                    const int p = fn >> 1, f = fn & 1;
                    mma16816(acc[mf][fn], al, bh[p][f], bh[p][f + 2]);
                }
            }
        }
        __syncthreads();
        if (kt + 2 < NCHUNK) load_chunk(kt + 2, kt & 1);
    }

    __half* Oh = (z == 0) ? g_qh : g_kh;
    __half* Ol = (z == 0) ? g_ql : g_kl;
    const int trow = lane >> 2;
    const int tcol = (lane & 3) * 2;
    #pragma unroll
    for (int mf = 0; mf < 2; ++mf) {
        #pragma unroll
        for (int fn = 0; fn < 8; ++fn) {
            int o = n0 + wn + fn * 8 + tcol;
            int h = o >> 6, cb = o & 63;
            #pragma unroll
            for (int half = 0; half < 2; ++half) {
                int row = m0 + wm + mf * 16 + trow + half * 8;
                int b = row >> 11, n = row & (NN - 1);
                size_t idx = (((size_t)(b * HH + h)) * NN + n) * HD + cb;
                uint32_t hp, lp;
                split2h(acc[mf][fn][half * 2], acc[mf][fn][half * 2 + 1], hp, lp);
                *reinterpret_cast<uint32_t*>(Oh + idx) = hp;
                *reinterpret_cast<uint32_t*>(Ol + idx) = lp;
            }
        }
    }
}

// ---------------------------------------------------------------------------
// V projection (unchanged).
// ---------------------------------------------------------------------------
#define V_STAGE_B (2 * T128_B)

__global__ __launch_bounds__(256, 2) void v_mma_kernel()
{
    extern __shared__ char smc[];
    const uint32_t sb = smem_u32(smc);

    const int tid = threadIdx.x;
    const int w = tid >> 5, lane = tid & 31;
    const int wm = (w >> 1) * 32;
    const int wn = (w & 1) * 64;
    const int n0 = blockIdx.x * 128;
    const int m0 = blockIdx.y * 128;

    const __half* __restrict__ Bhp = g_wh + (size_t)2 * WN;

    auto load_chunk = [&](int kt, int stage) {
        const int kb = kt * KC;
        const uint32_t st = sb + stage * V_STAGE_B;
        #pragma unroll
        for (int i = 0; i < 2; ++i) {
            int id = tid + i * 256;
            int r = id >> 2, c = id & 3;
            uint32_t doff = (uint32_t)(r * 80 + c * 16);
            cpa16(st + doff, g_xh + (size_t)(m0 + r) * DD + kb + c * 8);
            cpa16(st + T128_B + doff, Bhp + (size_t)(n0 + r) * DD + kb + c * 8);
        }
        cpa_commit();
    };

    float acc[2][8][4] = {};

    load_chunk(0, 0);
    load_chunk(1, 1);

    const int lrow = lane & 15;
    const int lcol = ((lane >> 4) & 1) * 8;

    for (int kt = 0; kt < NCHUNK; ++kt) {
        if (kt < NCHUNK - 1)
            asm volatile("cp.async.wait_group 1;" ::: "memory");
        else
            asm volatile("cp.async.wait_group 0;" ::: "memory");
        __syncthreads();

        const uint32_t st = sb + (kt & 1) * V_STAGE_B;

        #pragma unroll
        for (int ks = 0; ks < 2; ++ks) {
            const int kc = ks * 16 + lcol;
            uint32_t bh[4][4];
            #pragma unroll
            for (int fp = 0; fp < 4; ++fp) {
                uint32_t off = (uint32_t)((wn + fp * 16 + lrow) * SROW + kc) * 2;
                ldmx4(bh[fp], st + T128_B + off);
            }
            #pragma unroll
            for (int mf = 0; mf < 2; ++mf) {
                uint32_t ah[4];
                uint32_t off = (uint32_t)((wm + mf * 16 + lrow) * SROW + kc) * 2;
                ldmx4(ah, st + off);
                #pragma unroll
                for (int fn = 0; fn < 8; ++fn) {
                    const int p = fn >> 1, f = fn & 1;
                    mma16816(acc[mf][fn], ah, bh[p][f], bh[p][f + 2]);
                }
            }
        }
        __syncthreads();
        if (kt + 2 < NCHUNK) load_chunk(kt + 2, kt & 1);
    }

    const int trow = lane >> 2;
    const int tcol = (lane & 3) * 2;
    #pragma unroll
    for (int mf = 0; mf < 2; ++mf) {
        #pragma unroll
        for (int fn = 0; fn < 8; ++fn) {
            int o = n0 + wn + fn * 8 + tcol;
            int h = o >> 6, cb = o & 63;
            #pragma unroll
            for (int half = 0; half < 2; ++half) {
                int row = m0 + wm + mf * 16 + trow + half * 8;
                int b = row >> 11, n = row & (NN - 1);
                size_t idx = (((size_t)(b * HH + h)) * NN + n) * HD + cb;
                *reinterpret_cast<uint32_t*>(g_vh + idx) =
                    pack2h(acc[mf][fn][half * 2], acc[mf][fn][half * 2 + 1]);
            }
        }
    }
}

// ---------------------------------------------------------------------------
// Flash attention: R14 body; softmax retooled:
//  - P = ex2.approx.f16x2(pack(s - m))   (16 MUFU instead of 32)
//  - li via ones-matrix MMA into persistent fp32 accumulator (full row sums,
//    no FADD chain, no epilogue shuffles)
// ---------------------------------------------------------------------------
#define VROW 72
#define QT_B (64 * VROW * 2)
#define KVTILE_B (64 * VROW * 2)
#define KVSTAGE_B (3 * KVTILE_B)

__global__ __launch_bounds__(128, 3) void flash_mma_kernel(float* __restrict__ out)
{
    extern __shared__ char smc[];
    const uint32_t sb = smem_u32(smc);
    const uint32_t sQh = sb;
    const uint32_t sQl = sb + QT_B;
    const uint32_t sKV = sb + 2 * QT_B;

    const int tid = threadIdx.x, wid = tid >> 5, lane = tid & 31;
    const int bh = blockIdx.y;
    const int qt = (int)gridDim.x - 1 - (int)blockIdx.x;   // heavy tiles first
    const int qbase = qt * 64;
    const int wm = wid * 16;
    const int rowmax = qbase + wm + 15;

    const size_t base = (size_t)bh * NN * HD;
    const __half* __restrict__ Qhp = g_qh + base;
    const __half* __restrict__ Qlp = g_ql + base;
    const __half* __restrict__ Khp = g_kh + base;
    const __half* __restrict__ Klp = g_kl + base;
    const __half* __restrict__ Vhp = g_vh + base;

    auto load_kv = [&](int j, int stage) {
        const int kb = j * 64;
        const uint32_t st = sKV + stage * KVSTAGE_B;
        #pragma unroll
        for (int i = 0; i < 4; ++i) {
            int id = tid + i * 128;
            int r = id >> 3, c = id & 7;
            uint32_t doff = (uint32_t)(r * 144 + c * 16);
            size_t go = (size_t)(kb + r) * HD + c * 8;
            cpa16(st + 0 * KVTILE_B + doff, Khp + go);
            cpa16(st + 1 * KVTILE_B + doff, Klp + go);
            cpa16(st + 2 * KVTILE_B + doff, Vhp + go);
        }
        cpa_commit();
    };

    // Q tile (hi+lo) into smem; joins commit group 0
    #pragma unroll
    for (int i = 0; i < 4; ++i) {
        int id = tid + i * 128;
        int r = id >> 3, c = id & 7;
        uint32_t doff = (uint32_t)(r * 144 + c * 16);
        size_t go = (size_t)(qbase + r) * HD + c * 8;
        cpa16(sQh + doff, Qhp + go);
        cpa16(sQl + doff, Qlp + go);
    }

    float o[8][4] = {};
    float liacc[4] = {};           // c[0] = rowsum(r0), c[2] = rowsum(r0+8)
    float mi0 = -1e30f, mi1 = -1e30f;
    uint32_t mip;
    {
        __half2 t = __floats2half2_rn(-1e30f, -1e30f);
        mip = *reinterpret_cast<uint32_t*>(&t);
    }

    const int ntiles = qt + 1;
    load_kv(0, 0);
    if (ntiles > 1) load_kv(1, 1);

    const int lrow = lane & 15;
    const int lcol = ((lane >> 4) & 1) * 8;
    const int vrow_base = (lane & 7) + ((lane >> 3) & 1) * 8;
    const int vcol = ((lane >> 4) & 1) * 8;

    for (int j = 0; j < ntiles; ++j) {
        if (j < ntiles - 1)
            asm volatile("cp.async.wait_group 1;" ::: "memory");
        else
            asm volatile("cp.async.wait_group 0;" ::: "memory");
        __syncthreads();

        const int j64 = 64 * j;
        const int nlim = rowmax - j64;
        const uint32_t st = sKV + (j & 1) * KVSTAGE_B;

        float s[8][4] = {};

        if (j < qt) {
            // dense fast path: distance-8 MMA ordering
            #pragma unroll
            for (int kk = 0; kk < 4; ++kk) {
                const int kc = kk * 16 + lcol;
                uint32_t qoff = (uint32_t)((wm + lrow) * VROW + kc) * 2;
                uint32_t qhf[4], qlf[4];
                ldmx4(qhf, sQh + qoff);
                ldmx4(qlf, sQl + qoff);
                uint32_t bh_[4][4], bl_[4][4];
                #pragma unroll
                for (int np = 0; np < 4; ++np) {
                    uint32_t off = (uint32_t)((np * 16 + lrow) * VROW + kc) * 2;
                    ldmx4(bh_[np], st + 0 * KVTILE_B + off);
                    ldmx4(bl_[np], st + 1 * KVTILE_B + off);
                }
                #pragma unroll
                for (int np = 0; np < 4; ++np) {
                    mma16816(s[np*2 + 0], qhf, bh_[np][0], bh_[np][2]);
                    mma16816(s[np*2 + 1], qhf, bh_[np][1], bh_[np][3]);
                }
                #pragma unroll
                for (int np = 0; np < 4; ++np) {
                    mma16816(s[np*2 + 0], qhf, bl_[np][0], bl_[np][2]);
                    mma16816(s[np*2 + 1], qhf, bl_[np][1], bl_[np][3]);
                }
                #pragma unroll
                for (int np = 0; np < 4; ++np) {
                    mma16816(s[np*2 + 0], qlf, bh_[np][0], bh_[np][2]);
                    mma16816(s[np*2 + 1], qlf, bh_[np][1], bh_[np][3]);
                }
            }
        } else {
            // diagonal tile (masked)
            #pragma unroll
            for (int kk = 0; kk < 4; ++kk) {
                const int kc = kk * 16 + lcol;
                uint32_t qoff = (uint32_t)((wm + lrow) * VROW + kc) * 2;
                uint32_t qhf[4], qlf[4];
                ldmx4(qhf, sQh + qoff);
                ldmx4(qlf, sQl + qoff);
                #pragma unroll
                for (int np = 0; np < 4; ++np) {
                    if (np * 16 <= nlim) {
                        uint32_t bkh[4], bkl[4];
                        uint32_t off = (uint32_t)((np * 16 + lrow) * VROW + kc) * 2;
                        ldmx4(bkh, st + 0 * KVTILE_B + off);
                        ldmx4(bkl, st + 1 * KVTILE_B + off);
                        const int fn0 = np * 2;
                        mma16816(s[fn0 + 0], qhf, bkh[0], bkh[2]);
                        mma16816(s[fn0 + 1], qhf, bkh[1], bkh[3]);
                        mma16816(s[fn0 + 0], qhf, bkl[0], bkl[2]);
                        mma16816(s[fn0 + 1], qhf, bkl[1], bkl[3]);
                        mma16816(s[fn0 + 0], qlf, bkh[0], bkh[2]);
                        mma16816(s[fn0 + 1], qlf, bkh[1], bkh[3]);
                    }
                }
            }
            const int rg0 = qbase + wm + (lane >> 2);
            #pragma unroll
            for (int fn = 0; fn < 8; ++fn) {
                const int cb = j64 + fn * 8 + (lane & 3) * 2;
                if (cb + 0 > rg0)     s[fn][0] = -1e30f;
                if (cb + 1 > rg0)     s[fn][1] = -1e30f;
                if (cb + 0 > rg0 + 8) s[fn][2] = -1e30f;
                if (cb + 1 > rg0 + 8) s[fn][3] = -1e30f;
            }
        }

        // ---- softmax: packed max + conditional rescale ----
        {
            float m0n = mi0, m1n = mi1;
            #pragma unroll
            for (int fn = 0; fn < 8; ++fn) {
                m0n = fmaxf(m0n, fmaxf(s[fn][0], s[fn][1]));
                m1n = fmaxf(m1n, fmaxf(s[fn][2], s[fn][3]));
            }
            __half2 mp = __floats2half2_rn(m0n, m1n);
            uint32_t mu = *reinterpret_cast<uint32_t*>(&mp);
            uint32_t t1 = __shfl_xor_sync(0xffffffffu, mu, 1);
            mp = __hmax2(mp, *reinterpret_cast<__half2*>(&t1));
            mu = *reinterpret_cast<uint32_t*>(&mp);
            uint32_t t2 = __shfl_xor_sync(0xffffffffu, mu, 2);
            mp = __hmax2(mp, *reinterpret_cast<__half2*>(&t2));
            mu = *reinterpret_cast<uint32_t*>(&mp);

            const float m0f = __low2float(mp);
            const float m1f = __high2float(mp);

            if (mu != mip) {
                const float al0 = exp2f(mi0 - m0f);
                const float al1 = exp2f(mi1 - m1f);
                liacc[0] *= al0; liacc[2] *= al1;
                #pragma unroll
                for (int fn = 0; fn < 8; ++fn) {
                    o[fn][0] *= al0; o[fn][1] *= al0;
                    o[fn][2] *= al1; o[fn][3] *= al1;
                }
                mi0 = m0f; mi1 = m1f; mip = mu;
            }
        }

        // ---- P = ex2(s - m) directly in fp16x2 ----
        uint32_t ph[4][4];
        #pragma unroll
        for (int kk = 0; kk < 4; ++kk) {
            ph[kk][0] = hex2(pack2h(s[2*kk    ][0] - mi0, s[2*kk    ][1] - mi0));
            ph[kk][1] = hex2(pack2h(s[2*kk    ][2] - mi1, s[2*kk    ][3] - mi1));
            ph[kk][2] = hex2(pack2h(s[2*kk + 1][0] - mi0, s[2*kk + 1][1] - mi0));
            ph[kk][3] = hex2(pack2h(s[2*kk + 1][2] - mi1, s[2*kk + 1][3] - mi1));
        }

        // ---- li += P * ones (tensor pipe does the row sums) ----
        #pragma unroll
        for (int kk = 0; kk < 4; ++kk) {
            if (j < qt || kk * 16 <= nlim)
                mma16816(liacc, ph[kk], ONES2, ONES2);
        }

        // ---- O += P V ----
        if (j < qt) {
            #pragma unroll
            for (int kk = 0; kk < 4; ++kk) {
                uint32_t v0[4], v1[4], v2[4], v3[4];
                const int vrow = kk * 16 + vrow_base;
                uint32_t offb = (uint32_t)(vrow * VROW + vcol) * 2;
                ldmx4t(v0, st + 2 * KVTILE_B + offb + 0 * 32);
                ldmx4t(v1, st + 2 * KVTILE_B + offb + 1 * 32);
                ldmx4t(v2, st + 2 * KVTILE_B + offb + 2 * 32);
                ldmx4t(v3, st + 2 * KVTILE_B + offb + 3 * 32);
                mma16816(o[0], ph[kk], v0[0], v0[1]);
                mma16816(o[1], ph[kk], v0[2], v0[3]);
                mma16816(o[2], ph[kk], v1[0], v1[1]);
                mma16816(o[3], ph[kk], v1[2], v1[3]);
                mma16816(o[4], ph[kk], v2[0], v2[1]);
                mma16816(o[5], ph[kk], v2[2], v2[3]);
                mma16816(o[6], ph[kk], v3[0], v3[1]);
                mma16816(o[7], ph[kk], v3[2], v3[3]);
            }
        } else {
            #pragma unroll
            for (int kk = 0; kk < 4; ++kk) {
                if (kk * 16 <= nlim) {
                    #pragma unroll
                    for (int dp = 0; dp < 4; ++dp) {
                        const int vrow = kk * 16 + vrow_base;
                        uint32_t off = (uint32_t)(vrow * VROW + dp * 16 + vcol) * 2;
                        uint32_t vh_[4];
                        ldmx4t(vh_, st + 2 * KVTILE_B + off);
                        mma16816(o[dp*2 + 0], ph[kk], vh_[0], vh_[1]);
                        mma16816(o[dp*2 + 1], ph[kk], vh_[2], vh_[3]);
                    }
                }
            }
        }

        __syncthreads();
        if (j + 2 < ntiles) load_kv(j + 2, j & 1);
    }

    // ---- epilogue: li already complete per-thread (full row sums) ----
    const int b = bh / HH, h = bh % HH;
    const float inv0 = 1.0f / liacc[0], inv1 = 1.0f / liacc[2];
    const int r0 = qbase + wm + (lane >> 2);
    const int c0 = (lane & 3) * 2;
    #pragma unroll
    for (int fn = 0; fn < 8; ++fn) {
        const int col = h * HD + fn * 8 + c0;
        float* d0 = out + ((size_t)(b * NN + r0)) * DD + col;
        float* d1 = out + ((size_t)(b * NN + r0 + 8)) * DD + col;
        *reinterpret_cast<float2*>(d0) = make_float2(o[fn][0] * inv0, o[fn][1] * inv0);
        *reinterpret_cast<float2*>(d1) = make_float2(o[fn][2] * inv1, o[fn][3] * inv1);
    }
}

static const int QK_SMEM    = 2 * QK_STAGE_B;             // 81920
static const int V_SMEM     = 2 * V_STAGE_B;              // 40960
static const int FLASH_SMEM = 2 * QT_B + 2 * KVSTAGE_B;   // 73728

extern "C" void kernel_launch(void* const* d_in, const int* in_sizes, int n_in,
                              void* d_out, int out_size)
{
    const float* x  = (const float*)d_in[0];
    const float* Wq = (const float*)d_in[1];
    const float* Wk = (const float*)d_in[2];
    const float* Wv = (const float*)d_in[3];
    float* out = (float*)d_out;

    static cudaStream_t s_v = nullptr;
    static cudaEvent_t e_fork = nullptr, e_join = nullptr;
    if (s_v == nullptr) {
        cudaStreamCreateWithFlags(&s_v, cudaStreamNonBlocking);
        cudaEventCreateWithFlags(&e_fork, cudaEventDisableTiming);
        cudaEventCreateWithFlags(&e_join, cudaEventDisableTiming);
        cudaFuncSetAttribute(qk_mma_kernel, cudaFuncAttributeMaxDynamicSharedMemorySize, QK_SMEM);
        cudaFuncSetAttribute(v_mma_kernel, cudaFuncAttributeMaxDynamicSharedMemorySize, V_SMEM);
        cudaFuncSetAttribute(flash_mma_kernel, cudaFuncAttributeMaxDynamicSharedMemorySize, FLASH_SMEM);
    }

    int total4 = XN / 4 + 3 * (WN / 4);
    split_kernel<<<(total4 + 255) / 256, 256>>>(
        (const float4*)x, (const float4*)Wq, (const float4*)Wk, (const float4*)Wv);

    cudaEventRecord(e_fork, 0);
    cudaStreamWaitEvent(s_v, e_fork, 0);

    qk_mma_kernel<<<dim3(DD / 128, (BB * NN) / 128, 2), 256, QK_SMEM>>>();
    v_mma_kernel<<<dim3(DD / 128, (BB * NN) / 128), 256, V_SMEM, s_v>>>();

    cudaEventRecord(e_join, s_v);
    cudaStreamWaitEvent(0, e_join, 0);

    flash_mma_kernel<<<dim3(NN / 64, BH), 128, FLASH_SMEM>>>(out);
}